// round 12
// baseline (speedup 1.0000x reference)
#include <cuda_runtime.h>
#include <cuda_bf16.h>
#include <math.h>

// ---------------------------------------------------------------------------
// SecDecoder outputs (flattened, concatenated in tuple order)
//   rp        [total]     = (M @ arange(ncol)) / ncol
//   gaps_start[nseq]      = sa[start_row]/ncol
//   gaps_in   [n_keep]    = (sa[g+1]-sa[g]-1)/ncol, g not a seq boundary
//   gaps_end  [nseq]      = (ncol - sa[end_row] - 1)/ncol
//   col_dist  [ncol*nout] = softmax(columns @ W + b)
//
// SINGLE persistent kernel:
//   phase 1 (grid-stride units): unit 0 = cumsum+uniformity, units [1,129) =
//     col_dist, units [129,...) = soft_argmax rows (HBM-roofline stream,
//     inner loop unchanged from the measured-87%-of-HBM version).
//   grid barrier (sense-reversal, replay-safe, executed once per block).
//   phase 2: gaps, 4 per thread. Bounded barrier wait with a recompute-from-
//     inputs fallback keeps correctness even if co-residency breaks.
// ---------------------------------------------------------------------------

#define MAX_TOTAL 131072
#define MAX_NSEQ  1024
#define NOUT      26      // fixed by problem
#define KMAX      16      // dcol/32 (dcol = 512)
#define DBLOCKS   128     // coldist units (ncol/8)
#define ABASE     (1 + DBLOCKS)   // first A unit index

__device__ float    g_sa[MAX_TOTAL];  // soft_argmax values
__device__ int      g_cs[MAX_NSEQ];   // cumsum(sequence_lengths), int32
__device__ int      g_uniL;           // uniform length if all equal, else 0
__device__ unsigned g_arrive;         // barrier arrival counter (self-reset)
__device__ unsigned g_release;        // barrier release generation (monotonic)

// Dtype-agnostic sequence_lengths accessor (harness may pass int64 or int32).
// Lengths strictly positive; little-endian int64 => word[1]==0.
__device__ __forceinline__ bool sl_is_int64(const void* sl) {
    return ((const int*)sl)[1] == 0;
}
__device__ __forceinline__ int sl_get(const void* sl, bool is64, int i) {
    if (is64) return (int)((const long long*)sl)[i];
    return ((const int*)sl)[i];
}

// scalar row soft-argmax (fallback path only; correct, slow)
__device__ float row_sum_scalar(const float* __restrict__ M, int row, int ncol) {
    const float4* p = reinterpret_cast<const float4*>(M) + (size_t)row * (ncol >> 2);
    float s = 0.f;
    for (int k = 0; k < (ncol >> 2); k++) {
        float4 v = __ldg(p + k);
        float c = (float)(k << 2);
        s = fmaf(v.x, c,        s);
        s = fmaf(v.y, c + 1.0f, s);
        s = fmaf(v.z, c + 2.0f, s);
        s = fmaf(v.w, c + 3.0f, s);
    }
    return s;
}

// ---------------------------------------------------------------------------
__global__ void __launch_bounds__(256) persist_kernel(
    const float* __restrict__ M, float* __restrict__ out,
    const float* __restrict__ columns, const float* __restrict__ W,
    const float* __restrict__ b, const void* __restrict__ sl,
    int total, int ncol, int dcol, int nseq,
    float ncolf, float inv_ncol,
    int off_gs, int off_gin, int off_ge, int off_cd,
    int n_units, int nblocks)
{
    __shared__ unsigned snap_s;
    __shared__ int ok_s;

    int tid  = threadIdx.x;
    int warp = tid >> 5;
    int lane = tid & 31;

    if (tid == 0) snap_s = __ldcg(&g_release);   // pre-launch generation
    __syncthreads();
    unsigned snap = snap_s;

    // ========================= phase 1: units =========================
    for (int vb = blockIdx.x; vb < n_units; vb += nblocks) {
        if (vb >= ABASE) {
            // -------- A: soft_argmax, one warp per row (roofline loop) --------
            int row_i = (vb - ABASE) * 8 + warp;
            if (row_i < total) {
                const float4* row = reinterpret_cast<const float4*>(M)
                                  + (size_t)row_i * (ncol >> 2);
                float sum = 0.f;
                int nvec = ncol >> 2;
#pragma unroll 8
                for (int k = lane; k < nvec; k += 32) {
                    float4 v = __ldcs(row + k);    // read-once: evict-first
                    float c = (float)(k << 2);
                    sum = fmaf(v.x, c,        sum);
                    sum = fmaf(v.y, c + 1.0f, sum);
                    sum = fmaf(v.z, c + 2.0f, sum);
                    sum = fmaf(v.w, c + 3.0f, sum);
                }
#pragma unroll
                for (int o = 16; o; o >>= 1)
                    sum += __shfl_down_sync(0xffffffffu, sum, o);
                if (lane == 0) {
                    g_sa[row_i] = sum;
                    out[row_i]  = sum * inv_ncol;
                }
            }
        } else if (vb == 0) {
            // -------- cumsum via warp shuffle-scan + uniformity (warp 0) --------
            if (warp == 0) {
                bool is64 = sl_is_int64(sl);
                int L0 = sl_get(sl, is64, 0);
                int carry = 0;
                bool uni = true;
                int nchunks = (nseq + 31) >> 5;
                for (int c = 0; c < nchunks; c++) {
                    int i = (c << 5) + lane;
                    int v = (i < nseq) ? sl_get(sl, is64, i) : 0;
                    if (i < nseq && v != L0) uni = false;
#pragma unroll
                    for (int s = 1; s < 32; s <<= 1) {
                        int u = __shfl_up_sync(0xffffffffu, v, s);
                        if (lane >= s) v += u;
                    }
                    v += carry;
                    if (i < nseq) g_cs[i] = v;
                    carry = __shfl_sync(0xffffffffu, v, 31);
                }
                bool all_uni = __all_sync(0xffffffffu, uni);
                if (lane == 0) g_uniL = all_uni ? L0 : 0;
            }
        } else {
            // -------- D: col_dist, one warp per column-row --------
            int r = (vb - 1) * 8 + warp;
            if (r < ncol) {
                float x[KMAX];
                const float* crow = columns + (size_t)r * dcol;
#pragma unroll
                for (int k = 0; k < KMAX; k++)
                    x[k] = __ldg(crow + (k << 5) + lane);

                float acc[NOUT];
#pragma unroll
                for (int o = 0; o < NOUT; o++) acc[o] = 0.f;
#pragma unroll
                for (int k = 0; k < KMAX; k++) {
                    const float* wrow = W + (size_t)((k << 5) + lane) * NOUT;
                    float xv = x[k];
#pragma unroll
                    for (int o = 0; o < NOUT; o++)
                        acc[o] = fmaf(xv, __ldg(wrow + o), acc[o]);
                }
#pragma unroll
                for (int o = 0; o < NOUT; o++) {
#pragma unroll
                    for (int sft = 16; sft; sft >>= 1)
                        acc[o] += __shfl_xor_sync(0xffffffffu, acc[o], sft);
                }
                float val = -INFINITY;
#pragma unroll
                for (int o = 0; o < NOUT; o++)
                    if (lane == o) val = acc[o];
                bool active = (lane < NOUT);
                if (active) val += __ldg(b + lane);
                else        val  = -INFINITY;
                float m = val;
#pragma unroll
                for (int sft = 16; sft; sft >>= 1)
                    m = fmaxf(m, __shfl_xor_sync(0xffffffffu, m, sft));
                float e = active ? expf(val - m) : 0.f;
                float sum = e;
#pragma unroll
                for (int sft = 16; sft; sft >>= 1)
                    sum += __shfl_xor_sync(0xffffffffu, sum, sft);
                if (active) out[off_cd + (size_t)r * NOUT + lane] = e / sum;
            }
        }
    }

    // ===================== grid barrier (once per block) =====================
    __syncthreads();
    if (tid == 0) {
        __threadfence();                               // publish phase-1 stores
        unsigned old = atomicAdd(&g_arrive, 1u);
        int ok = 1;
        if (old == (unsigned)(nblocks - 1)) {
            __stcg(&g_arrive, 0u);                     // reset for next replay
            __threadfence();
            atomicAdd(&g_release, 1u);                 // release generation++
        } else {
            ok = 0;
            for (long it = 0; it < 400000; ++it) {     // ~50ms bound
                if (__ldcg(&g_release) != snap) { ok = 1; break; }
                __nanosleep(128);
            }
        }
        ok_s = ok;
    }
    __syncthreads();
    int ok = ok_s;
    if (ok) __threadfence();                           // acquire phase-1 stores

    // ========================= phase 2: gaps =========================
    int ngaps   = total - 1;
    int ngroups = (ngaps + 3) >> 2;
    int span    = ngroups > nseq ? ngroups : nseq;

    for (int t = blockIdx.x * 256 + tid; t < span; t += nblocks * 256) {
        if (ok) {
            int L = g_uniL;
            if (L > 0) {
                if (t < nseq) {
                    int row0 = t * L;
                    int rowe = row0 + L - 1;
                    out[off_gs + t] = __ldg(&g_sa[row0]) * inv_ncol;
                    out[off_ge + t] = (ncolf - __ldg(&g_sa[rowe]) - 1.0f) * inv_ncol;
                }
                int g0 = t << 2;
                if (g0 >= ngaps) continue;
                if (g0 + 4 <= ngaps) {
                    float4 v = *reinterpret_cast<const float4*>(&g_sa[g0]);
                    float sa[5] = { v.x, v.y, v.z, v.w, __ldg(&g_sa[g0 + 4]) };
#pragma unroll
                    for (int i = 0; i < 4; i++) {
                        int g = g0 + i;
                        int cnt = g / L;
                        if (cnt > nseq - 1) cnt = nseq - 1;
                        bool removed = (cnt < nseq - 1) && ((cnt + 1) * L == g + 1);
                        if (!removed)
                            out[off_gin + (g - cnt)] =
                                (sa[i + 1] - sa[i] - 1.0f) * inv_ncol;
                    }
                } else {
                    for (int g = g0; g < ngaps; g++) {
                        int cnt = g / L;
                        if (cnt > nseq - 1) cnt = nseq - 1;
                        bool removed = (cnt < nseq - 1) && ((cnt + 1) * L == g + 1);
                        if (!removed) {
                            float gap = __ldg(&g_sa[g + 1]) - __ldg(&g_sa[g]) - 1.0f;
                            out[off_gin + (g - cnt)] = gap * inv_ncol;
                        }
                    }
                }
            } else {
                // non-uniform lengths: binary search over g_cs
                if (t < nseq) {
                    int cs_t = __ldg(&g_cs[t]);
                    int row0 = (t == 0) ? 0 : __ldg(&g_cs[t - 1]);
                    out[off_gs + t] = __ldg(&g_sa[row0]) * inv_ncol;
                    out[off_ge + t] = (ncolf - __ldg(&g_sa[cs_t - 1]) - 1.0f) * inv_ncol;
                }
                int g0 = t << 2;
                for (int g = g0; g < g0 + 4 && g < ngaps; g++) {
                    int lo = 0, hi = nseq - 1;
                    while (lo < hi) {
                        int mid = (lo + hi) >> 1;
                        if (__ldg(&g_cs[mid]) <= g) lo = mid + 1; else hi = mid;
                    }
                    int cnt = lo;
                    bool removed = (cnt < nseq - 1) && (__ldg(&g_cs[cnt]) == g + 1);
                    if (!removed) {
                        float gap = __ldg(&g_sa[g + 1]) - __ldg(&g_sa[g]) - 1.0f;
                        out[off_gin + (g - cnt)] = gap * inv_ncol;
                    }
                }
            }
        } else {
            // -------- fallback: recompute from primary inputs (never in
            // practice; guarantees correctness if co-residency breaks) --------
            bool is64 = sl_is_int64(sl);
            if (t < nseq) {
                long long cs = 0;
                for (int k = 0; k <= t; k++) cs += sl_get(sl, is64, k);
                int row0 = (int)(cs - sl_get(sl, is64, t));
                int rowe = (int)(cs - 1);
                out[off_gs + t] = row_sum_scalar(M, row0, ncol) * inv_ncol;
                out[off_ge + t] =
                    (ncolf - row_sum_scalar(M, rowe, ncol) - 1.0f) * inv_ncol;
            }
            int g0 = t << 2;
            for (int g = g0; g < g0 + 4 && g < ngaps; g++) {
                long long cs = 0;
                int cnt = 0;
                for (int k = 0; k < nseq - 1; k++) {
                    cs += sl_get(sl, is64, k);
                    if (cs <= g) cnt++; else break;
                }
                bool removed = (cnt < nseq - 1) && (cs == (long long)g + 1);
                if (!removed) {
                    float gap = row_sum_scalar(M, g + 1, ncol)
                              - row_sum_scalar(M, g, ncol) - 1.0f;
                    out[off_gin + (g - cnt)] = gap * inv_ncol;
                }
            }
        }
    }
}

// ---------------------------------------------------------------------------
extern "C" void kernel_launch(void* const* d_in, const int* in_sizes, int n_in,
                              void* d_out, int out_size)
{
    const float* M    = (const float*)d_in[0];
    const float* cols = (const float*)d_in[1];
    const void*  sl   = d_in[2];            // int32 or int64, probed on device
    const float* W    = (const float*)d_in[3];
    const float* b    = (const float*)d_in[4];
    float*       out  = (float*)d_out;

    int nout  = in_sizes[4];                // 26
    int dcol  = in_sizes[3] / nout;         // 512
    int ncol  = in_sizes[1] / dcol;         // 1024
    int total = in_sizes[0] / ncol;         // 100000
    int nseq  = in_sizes[2];                // 500

    float ncolf    = (float)ncol;
    float inv_ncol = 1.0f / ncolf;

    int n_keep  = (total - 1) - (nseq - 1);
    int off_gs  = total;
    int off_gin = total + nseq;
    int off_ge  = off_gin + n_keep;
    int off_cd  = off_ge + nseq;

    int a_units = (total + 7) / 8;          // 12500
    int n_units = ABASE + a_units;          // 12629

    // size the persistent grid to guaranteed co-residency
    int nb_sm = 0;
    cudaOccupancyMaxActiveBlocksPerMultiprocessor(&nb_sm, persist_kernel, 256, 0);
    int nsm = 0;
    cudaDeviceGetAttribute(&nsm, cudaDevAttrMultiProcessorCount, 0);
    int nb = nb_sm * nsm;
    if (nb <= 0) nb = 148;
    if (nb > n_units) nb = n_units;

    persist_kernel<<<nb, 256>>>(
        M, out, cols, W, b, sl,
        total, ncol, dcol, nseq, ncolf, inv_ncol,
        off_gs, off_gin, off_ge, off_cd,
        n_units, nb);
}

// round 13
// speedup vs baseline: 1.0410x; 1.0410x over previous
#include <cuda_runtime.h>
#include <cuda_bf16.h>
#include <math.h>

// ---------------------------------------------------------------------------
// SecDecoder outputs (flattened, concatenated in tuple order)
//   rp        [total]     = (M @ arange(ncol)) / ncol
//   gaps_start[nseq]      = sa[start_row]/ncol
//   gaps_in   [n_keep]    = (sa[g+1]-sa[g]-1)/ncol, g not a seq boundary
//   gaps_end  [nseq]      = (ncol - sa[end_row] - 1)/ncol
//   col_dist  [ncol*nout] = softmax(columns @ W + b)
//
// SINGLE persistent kernel, register-capped with __launch_bounds__(256, 6)
// (<=42 regs) so the A-stream keeps 48 warps/SM. Phase 1 (grid-stride
// units): unit 0 = cumsum+uniformity, units [1,129) = col_dist (spills a
// little to local — hidden), units [129,...) = soft_argmax rows (HBM
// roofline). One sense-reversal grid barrier (replay-safe). Phase 2: gaps,
// 4 per thread. Bounded barrier wait + recompute-from-inputs fallback keeps
// correctness even if co-residency ever breaks (never taken: grid is sized
// by the occupancy API for this exact kernel).
// ---------------------------------------------------------------------------

#define MAX_TOTAL 131072
#define MAX_NSEQ  1024
#define NOUT      26      // fixed by problem
#define KMAX      16      // dcol/32 (dcol = 512)
#define DBLOCKS   128     // coldist units (ncol/8)
#define ABASE     (1 + DBLOCKS)   // first A unit index

__device__ float    g_sa[MAX_TOTAL];  // soft_argmax values
__device__ int      g_cs[MAX_NSEQ];   // cumsum(sequence_lengths), int32
__device__ int      g_uniL;           // uniform length if all equal, else 0
__device__ unsigned g_arrive;         // barrier arrival counter (self-reset)
__device__ unsigned g_release;        // barrier release generation (monotonic)

// Dtype-agnostic sequence_lengths accessor (harness may pass int64 or int32).
// Lengths strictly positive; little-endian int64 => word[1]==0.
__device__ __forceinline__ bool sl_is_int64(const void* sl) {
    return ((const int*)sl)[1] == 0;
}
__device__ __forceinline__ int sl_get(const void* sl, bool is64, int i) {
    if (is64) return (int)((const long long*)sl)[i];
    return ((const int*)sl)[i];
}

// scalar row soft-argmax (fallback path only; correct, slow)
__device__ __noinline__ float row_sum_scalar(
    const float* __restrict__ M, int row, int ncol)
{
    const float4* p = reinterpret_cast<const float4*>(M) + (size_t)row * (ncol >> 2);
    float s = 0.f;
    for (int k = 0; k < (ncol >> 2); k++) {
        float4 v = __ldg(p + k);
        float c = (float)(k << 2);
        s = fmaf(v.x, c,        s);
        s = fmaf(v.y, c + 1.0f, s);
        s = fmaf(v.z, c + 2.0f, s);
        s = fmaf(v.w, c + 3.0f, s);
    }
    return s;
}

// ---------------------------------------------------------------------------
__global__ void __launch_bounds__(256, 6) persist_kernel(
    const float* __restrict__ M, float* __restrict__ out,
    const float* __restrict__ columns, const float* __restrict__ W,
    const float* __restrict__ b, const void* __restrict__ sl,
    int total, int ncol, int dcol, int nseq,
    float ncolf, float inv_ncol,
    int off_gs, int off_gin, int off_ge, int off_cd,
    int n_units, int nblocks)
{
    __shared__ unsigned snap_s;
    __shared__ int ok_s;

    int tid  = threadIdx.x;
    int warp = tid >> 5;
    int lane = tid & 31;

    if (tid == 0) snap_s = __ldcg(&g_release);   // pre-launch generation
    __syncthreads();
    unsigned snap = snap_s;

    // ========================= phase 1: units =========================
    for (int vb = blockIdx.x; vb < n_units; vb += nblocks) {
        if (vb >= ABASE) {
            // -------- A: soft_argmax, one warp per row (roofline loop) --------
            int row_i = (vb - ABASE) * 8 + warp;
            if (row_i < total) {
                const float4* row = reinterpret_cast<const float4*>(M)
                                  + (size_t)row_i * (ncol >> 2);
                float sum = 0.f;
                int nvec = ncol >> 2;
#pragma unroll 8
                for (int k = lane; k < nvec; k += 32) {
                    float4 v = __ldcs(row + k);    // read-once: evict-first
                    float c = (float)(k << 2);
                    sum = fmaf(v.x, c,        sum);
                    sum = fmaf(v.y, c + 1.0f, sum);
                    sum = fmaf(v.z, c + 2.0f, sum);
                    sum = fmaf(v.w, c + 3.0f, sum);
                }
#pragma unroll
                for (int o = 16; o; o >>= 1)
                    sum += __shfl_down_sync(0xffffffffu, sum, o);
                if (lane == 0) {
                    g_sa[row_i] = sum;
                    out[row_i]  = sum * inv_ncol;
                }
            }
        } else if (vb == 0) {
            // ------ cumsum via warp shuffle-scan + uniformity (warp 0) ------
            if (warp == 0) {
                bool is64 = sl_is_int64(sl);
                int L0 = sl_get(sl, is64, 0);
                int carry = 0;
                bool uni = true;
                int nchunks = (nseq + 31) >> 5;
                for (int c = 0; c < nchunks; c++) {
                    int i = (c << 5) + lane;
                    int v = (i < nseq) ? sl_get(sl, is64, i) : 0;
                    if (i < nseq && v != L0) uni = false;
#pragma unroll
                    for (int s = 1; s < 32; s <<= 1) {
                        int u = __shfl_up_sync(0xffffffffu, v, s);
                        if (lane >= s) v += u;
                    }
                    v += carry;
                    if (i < nseq) g_cs[i] = v;
                    carry = __shfl_sync(0xffffffffu, v, 31);
                }
                bool all_uni = __all_sync(0xffffffffu, uni);
                if (lane == 0) g_uniL = all_uni ? L0 : 0;
            }
        } else {
            // -------- D: col_dist, one warp per column-row --------
            // (may spill a few regs under the 42-reg cap; hidden under A)
            int r = (vb - 1) * 8 + warp;
            if (r < ncol) {
                float x[KMAX];
                const float* crow = columns + (size_t)r * dcol;
#pragma unroll
                for (int k = 0; k < KMAX; k++)
                    x[k] = __ldg(crow + (k << 5) + lane);

                float acc[NOUT];
#pragma unroll
                for (int o = 0; o < NOUT; o++) acc[o] = 0.f;
#pragma unroll
                for (int k = 0; k < KMAX; k++) {
                    const float* wrow = W + (size_t)((k << 5) + lane) * NOUT;
                    float xv = x[k];
#pragma unroll
                    for (int o = 0; o < NOUT; o++)
                        acc[o] = fmaf(xv, __ldg(wrow + o), acc[o]);
                }
#pragma unroll
                for (int o = 0; o < NOUT; o++) {
#pragma unroll
                    for (int sft = 16; sft; sft >>= 1)
                        acc[o] += __shfl_xor_sync(0xffffffffu, acc[o], sft);
                }
                float val = -INFINITY;
#pragma unroll
                for (int o = 0; o < NOUT; o++)
                    if (lane == o) val = acc[o];
                bool active = (lane < NOUT);
                if (active) val += __ldg(b + lane);
                else        val  = -INFINITY;
                float m = val;
#pragma unroll
                for (int sft = 16; sft; sft >>= 1)
                    m = fmaxf(m, __shfl_xor_sync(0xffffffffu, m, sft));
                float e = active ? expf(val - m) : 0.f;
                float sum = e;
#pragma unroll
                for (int sft = 16; sft; sft >>= 1)
                    sum += __shfl_xor_sync(0xffffffffu, sum, sft);
                if (active) out[off_cd + (size_t)r * NOUT + lane] = e / sum;
            }
        }
    }

    // ===================== grid barrier (once per block) =====================
    __syncthreads();
    if (tid == 0) {
        __threadfence();                               // publish phase-1 stores
        unsigned old = atomicAdd(&g_arrive, 1u);
        int ok = 1;
        if (old == (unsigned)(nblocks - 1)) {
            __stcg(&g_arrive, 0u);                     // reset for next replay
            __threadfence();
            atomicAdd(&g_release, 1u);                 // release generation++
        } else {
            ok = 0;
            for (long it = 0; it < 400000; ++it) {     // ~50ms bound
                if (__ldcg(&g_release) != snap) { ok = 1; break; }
                __nanosleep(128);
            }
        }
        ok_s = ok;
    }
    __syncthreads();
    int ok = ok_s;
    if (ok) __threadfence();                           // acquire phase-1 stores

    // ========================= phase 2: gaps =========================
    int ngaps   = total - 1;
    int ngroups = (ngaps + 3) >> 2;
    int span    = ngroups > nseq ? ngroups : nseq;

    for (int t = blockIdx.x * 256 + tid; t < span; t += nblocks * 256) {
        if (ok) {
            int L = g_uniL;
            if (L > 0) {
                if (t < nseq) {
                    int row0 = t * L;
                    int rowe = row0 + L - 1;
                    out[off_gs + t] = __ldg(&g_sa[row0]) * inv_ncol;
                    out[off_ge + t] = (ncolf - __ldg(&g_sa[rowe]) - 1.0f) * inv_ncol;
                }
                int g0 = t << 2;
                if (g0 >= ngaps) continue;
                if (g0 + 4 <= ngaps) {
                    float4 v = *reinterpret_cast<const float4*>(&g_sa[g0]);
                    float sa[5] = { v.x, v.y, v.z, v.w, __ldg(&g_sa[g0 + 4]) };
#pragma unroll
                    for (int i = 0; i < 4; i++) {
                        int g = g0 + i;
                        int cnt = g / L;
                        if (cnt > nseq - 1) cnt = nseq - 1;
                        bool removed = (cnt < nseq - 1) && ((cnt + 1) * L == g + 1);
                        if (!removed)
                            out[off_gin + (g - cnt)] =
                                (sa[i + 1] - sa[i] - 1.0f) * inv_ncol;
                    }
                } else {
                    for (int g = g0; g < ngaps; g++) {
                        int cnt = g / L;
                        if (cnt > nseq - 1) cnt = nseq - 1;
                        bool removed = (cnt < nseq - 1) && ((cnt + 1) * L == g + 1);
                        if (!removed) {
                            float gap = __ldg(&g_sa[g + 1]) - __ldg(&g_sa[g]) - 1.0f;
                            out[off_gin + (g - cnt)] = gap * inv_ncol;
                        }
                    }
                }
            } else {
                // non-uniform lengths: binary search over g_cs
                if (t < nseq) {
                    int cs_t = __ldg(&g_cs[t]);
                    int row0 = (t == 0) ? 0 : __ldg(&g_cs[t - 1]);
                    out[off_gs + t] = __ldg(&g_sa[row0]) * inv_ncol;
                    out[off_ge + t] = (ncolf - __ldg(&g_sa[cs_t - 1]) - 1.0f) * inv_ncol;
                }
                int g0 = t << 2;
                for (int g = g0; g < g0 + 4 && g < ngaps; g++) {
                    int lo = 0, hi = nseq - 1;
                    while (lo < hi) {
                        int mid = (lo + hi) >> 1;
                        if (__ldg(&g_cs[mid]) <= g) lo = mid + 1; else hi = mid;
                    }
                    int cnt = lo;
                    bool removed = (cnt < nseq - 1) && (__ldg(&g_cs[cnt]) == g + 1);
                    if (!removed) {
                        float gap = __ldg(&g_sa[g + 1]) - __ldg(&g_sa[g]) - 1.0f;
                        out[off_gin + (g - cnt)] = gap * inv_ncol;
                    }
                }
            }
        } else {
            // -------- fallback: recompute from primary inputs (never taken;
            // guarantees correctness if co-residency breaks). Spills freely. --
            bool is64 = sl_is_int64(sl);
            if (t < nseq) {
                long long cs = 0;
                for (int k = 0; k <= t; k++) cs += sl_get(sl, is64, k);
                int row0 = (int)(cs - sl_get(sl, is64, t));
                int rowe = (int)(cs - 1);
                out[off_gs + t] = row_sum_scalar(M, row0, ncol) * inv_ncol;
                out[off_ge + t] =
                    (ncolf - row_sum_scalar(M, rowe, ncol) - 1.0f) * inv_ncol;
            }
            int g0 = t << 2;
            for (int g = g0; g < g0 + 4 && g < ngaps; g++) {
                long long cs = 0;
                int cnt = 0;
                for (int k = 0; k < nseq - 1; k++) {
                    cs += sl_get(sl, is64, k);
                    if (cs <= g) cnt++; else break;
                }
                bool removed = (cnt < nseq - 1) && (cs == (long long)g + 1);
                if (!removed) {
                    float gap = row_sum_scalar(M, g + 1, ncol)
                              - row_sum_scalar(M, g, ncol) - 1.0f;
                    out[off_gin + (g - cnt)] = gap * inv_ncol;
                }
            }
        }
    }
}

// ---------------------------------------------------------------------------
extern "C" void kernel_launch(void* const* d_in, const int* in_sizes, int n_in,
                              void* d_out, int out_size)
{
    const float* M    = (const float*)d_in[0];
    const float* cols = (const float*)d_in[1];
    const void*  sl   = d_in[2];            // int32 or int64, probed on device
    const float* W    = (const float*)d_in[3];
    const float* b    = (const float*)d_in[4];
    float*       out  = (float*)d_out;

    int nout  = in_sizes[4];                // 26
    int dcol  = in_sizes[3] / nout;         // 512
    int ncol  = in_sizes[1] / dcol;         // 1024
    int total = in_sizes[0] / ncol;         // 100000
    int nseq  = in_sizes[2];                // 500

    float ncolf    = (float)ncol;
    float inv_ncol = 1.0f / ncolf;

    int n_keep  = (total - 1) - (nseq - 1);
    int off_gs  = total;
    int off_gin = total + nseq;
    int off_ge  = off_gin + n_keep;
    int off_cd  = off_ge + nseq;

    int a_units = (total + 7) / 8;          // 12500
    int n_units = ABASE + a_units;          // 12629

    // size the persistent grid to guaranteed co-residency (for THIS kernel,
    // with its launch-bounds register cap)
    int nb_sm = 0;
    cudaOccupancyMaxActiveBlocksPerMultiprocessor(&nb_sm, persist_kernel, 256, 0);
    int nsm = 0;
    cudaDeviceGetAttribute(&nsm, cudaDevAttrMultiProcessorCount, 0);
    int nb = nb_sm * nsm;
    if (nb <= 0) nb = 148;
    if (nb > n_units) nb = n_units;

    persist_kernel<<<nb, 256>>>(
        M, out, cols, W, b, sl,
        total, ncol, dcol, nseq, ncolf, inv_ncol,
        off_gs, off_gin, off_ge, off_cd,
        n_units, nb);
}

// round 14
// speedup vs baseline: 1.1882x; 1.1414x over previous
#include <cuda_runtime.h>
#include <cuda_bf16.h>
#include <math.h>

// ---------------------------------------------------------------------------
// SecDecoder outputs (flattened, concatenated in tuple order)
//   rp        [total]     = (M @ arange(ncol)) / ncol
//   gaps_start[nseq]      = sa[start_row]/ncol
//   gaps_in   [n_keep]    = (sa[g+1]-sa[g]-1)/ncol, g not a seq boundary
//   gaps_end  [nseq]      = (ncol - sa[end_row] - 1)/ncol
//   col_dist  [ncol*nout] = softmax(columns @ W + b)
//
// ONE kernel, R8's one-unit-per-block dispatch shape (the grid-stride
// monolith measured 30% slower streaming; avoided):
//   block 0                      : cumsum + uniformity -> g_cs, g_meta
//   blocks [1, 1+DBLOCKS)        : col_dist
//   blocks [ABASE, ABASE+nA)     : soft_argmax, 8 rows/block; each block
//                                  publishes a per-block done flag
//                                  (syncthreads + 1 fence + 1 store)
//   blocks [ABASE+nA, ...)       : gap blocks — dispatched LAST by block
//                                  index, so they ramp during ad's tail;
//                                  spin on the 2-3 flags they need
//                                  (monotonic flags => replays never spin)
// ---------------------------------------------------------------------------

#define MAX_TOTAL 131072
#define MAX_NSEQ  1024
#define NOUT      26      // fixed by problem
#define KMAX      16      // dcol/32 (dcol = 512)
#define DBLOCKS   128     // coldist blocks (ncol/8)
#define ABASE     (1 + DBLOCKS)
#define MAX_ABLK  (MAX_TOTAL / 8)
#define SPIN_MAX  200000  // ~25ms bound; provably never reached

__device__ float g_sa[MAX_TOTAL];     // soft_argmax values
__device__ int   g_blkflag[MAX_ABLK]; // per-A-block done flags (monotonic)
__device__ int   g_cs[MAX_NSEQ];      // cumsum(sequence_lengths), int32
__device__ int   g_meta;              // 0 = not ready; else 1 + (uniform? L : 0)

// Dtype-agnostic sequence_lengths accessor (harness may pass int64 or int32).
// Lengths strictly positive; little-endian int64 => word[1]==0.
__device__ __forceinline__ bool sl_is_int64(const void* sl) {
    return ((const int*)sl)[1] == 0;
}
__device__ __forceinline__ int sl_get(const void* sl, bool is64, int i) {
    if (is64) return (int)((const long long*)sl)[i];
    return ((const int*)sl)[i];
}

// fallback only (never taken: gap blocks dispatch after all A blocks)
__device__ __noinline__ float row_sum_scalar(
    const float* __restrict__ M, int row, int ncol)
{
    const float4* p = reinterpret_cast<const float4*>(M) + (size_t)row * (ncol >> 2);
    float s = 0.f;
    for (int k = 0; k < (ncol >> 2); k++) {
        float4 v = __ldg(p + k);
        float c = (float)(k << 2);
        s = fmaf(v.x, c, s); s = fmaf(v.y, c + 1.0f, s);
        s = fmaf(v.z, c + 2.0f, s); s = fmaf(v.w, c + 3.0f, s);
    }
    return s;
}

// spin until the A-block covering `row` has published; returns true if set
__device__ __forceinline__ bool wait_row(int row) {
    const int* f = &g_blkflag[row >> 3];
    if (__ldcg(f)) return true;
    for (int it = 0; it < SPIN_MAX; ++it) {
        if (__ldcg(f)) return true;
        __nanosleep(128);
    }
    return false;
}
// read sa[row]; flag known-set (caller fenced) or recompute
__device__ __forceinline__ float sa_of(const float* M, int row, int ncol, bool ok) {
    return ok ? __ldcg(&g_sa[row]) : row_sum_scalar(M, row, ncol);
}

// ---------------------------------------------------------------------------
__global__ void __launch_bounds__(256, 4) fused_kernel(
    const float* __restrict__ M, float* __restrict__ out,
    const float* __restrict__ columns, const float* __restrict__ W,
    const float* __restrict__ b, const void* __restrict__ sl,
    int total, int ncol, int dcol, int nseq,
    float ncolf, float inv_ncol,
    int off_gs, int off_gin, int off_ge, int off_cd,
    int n_ablocks)
{
    int tid  = threadIdx.x;
    int warp = tid >> 5;
    int lane = tid & 31;
    int gapbase = ABASE + n_ablocks;

    if (blockIdx.x >= (unsigned)gapbase) {
        // ================= GAP blocks (dispatched last) =================
        int t = (blockIdx.x - gapbase) * 256 + tid;
        int ngaps = total - 1;

        // metadata (cumsum block finished long ago; first poll hits)
        int meta = __ldcg(&g_meta);
        for (int it = 0; meta == 0 && it < SPIN_MAX; ++it) {
            __nanosleep(128);
            meta = __ldcg(&g_meta);
        }
        if (meta == 0) meta = 1;              // degenerate; forces general path
        int L = meta - 1;

        if (L > 0) {
            // -------------------- uniform fast path --------------------
            bool okb = true;
            int r0 = 0, r1 = 0;
            if (t < nseq) {
                r0 = t * L; r1 = r0 + L - 1;
                okb  = wait_row(r0);
                okb &= wait_row(r1);
            }
            int g0 = t << 2;
            bool okg = true;
            if (g0 < ngaps) {
                int glast = g0 + 4; if (glast > ngaps) glast = ngaps;
                okg  = wait_row(g0);
                okg &= wait_row(glast);
            }
            __threadfence();                  // acquire all observed flags

            if (t < nseq) {
                out[off_gs + t] = sa_of(M, r0, ncol, okb) * inv_ncol;
                out[off_ge + t] = (ncolf - sa_of(M, r1, ncol, okb) - 1.0f) * inv_ncol;
            }
            if (g0 >= ngaps) return;

            if (okg && g0 + 4 <= ngaps) {
                float4 v = *reinterpret_cast<const float4*>(&g_sa[g0]);
                float sa[5] = { v.x, v.y, v.z, v.w, __ldcg(&g_sa[g0 + 4]) };
#pragma unroll
                for (int i = 0; i < 4; i++) {
                    int g = g0 + i;
                    int cnt = g / L;
                    if (cnt > nseq - 1) cnt = nseq - 1;
                    bool removed = (cnt < nseq - 1) && ((cnt + 1) * L == g + 1);
                    if (!removed)
                        out[off_gin + (g - cnt)] = (sa[i + 1] - sa[i] - 1.0f) * inv_ncol;
                }
            } else {
                for (int g = g0; g < g0 + 4 && g < ngaps; g++) {
                    int cnt = g / L;
                    if (cnt > nseq - 1) cnt = nseq - 1;
                    bool removed = (cnt < nseq - 1) && ((cnt + 1) * L == g + 1);
                    if (!removed) {
                        float gap = sa_of(M, g + 1, ncol, okg) - sa_of(M, g, ncol, okg) - 1.0f;
                        out[off_gin + (g - cnt)] = gap * inv_ncol;
                    }
                }
            }
        } else {
            // ---------------- general path (non-uniform) ----------------
            __threadfence();                  // acquire g_cs
            if (t < nseq) {
                int cs_t = __ldcg(&g_cs[t]);
                int r0 = (t == 0) ? 0 : __ldcg(&g_cs[t - 1]);
                int r1 = cs_t - 1;
                bool okb = wait_row(r0) & wait_row(r1);
                __threadfence();
                out[off_gs + t] = sa_of(M, r0, ncol, okb) * inv_ncol;
                out[off_ge + t] = (ncolf - sa_of(M, r1, ncol, okb) - 1.0f) * inv_ncol;
            }
            int g0 = t << 2;
            for (int g = g0; g < g0 + 4 && g < ngaps; g++) {
                int lo = 0, hi = nseq - 1;
                while (lo < hi) {
                    int mid = (lo + hi) >> 1;
                    if (__ldcg(&g_cs[mid]) <= g) lo = mid + 1; else hi = mid;
                }
                int cnt = lo;
                bool removed = (cnt < nseq - 1) && (__ldcg(&g_cs[cnt]) == g + 1);
                if (!removed) {
                    bool ok = wait_row(g) & wait_row(g + 1);
                    __threadfence();
                    float gap = sa_of(M, g + 1, ncol, ok) - sa_of(M, g, ncol, ok) - 1.0f;
                    out[off_gin + (g - cnt)] = gap * inv_ncol;
                }
            }
        }
        return;
    }

    if (blockIdx.x >= ABASE) {
        // ============ A: soft_argmax, one warp per row (roofline) ============
        int a = blockIdx.x - ABASE;
        int row_i = a * 8 + warp;
        if (row_i < total) {
            const float4* row = reinterpret_cast<const float4*>(M)
                              + (size_t)row_i * (ncol >> 2);
            float sum = 0.f;
            int nvec = ncol >> 2;
#pragma unroll 8
            for (int k = lane; k < nvec; k += 32) {
                float4 v = __ldcs(row + k);    // read-once: evict-first
                float c = (float)(k << 2);
                sum = fmaf(v.x, c,        sum);
                sum = fmaf(v.y, c + 1.0f, sum);
                sum = fmaf(v.z, c + 2.0f, sum);
                sum = fmaf(v.w, c + 3.0f, sum);
            }
#pragma unroll
            for (int o = 16; o; o >>= 1)
                sum += __shfl_down_sync(0xffffffffu, sum, o);
            if (lane == 0) {
                g_sa[row_i] = sum;
                out[row_i]  = sum * inv_ncol;
            }
        }
        // publish: block-level release (decoupled-lookback producer idiom)
        __syncthreads();
        if (tid == 0) {
            __threadfence();
            __stcg(&g_blkflag[a], 1);
        }
        return;
    }

    if (blockIdx.x == 0) {
        // ------- cumsum via warp shuffle-scan + uniformity (warp 0) -------
        if (warp == 0) {
            bool is64 = sl_is_int64(sl);
            int L0 = sl_get(sl, is64, 0);
            int carry = 0;
            bool uni = true;
            int nchunks = (nseq + 31) >> 5;
            for (int c = 0; c < nchunks; c++) {
                int i = (c << 5) + lane;
                int v = (i < nseq) ? sl_get(sl, is64, i) : 0;
                if (i < nseq && v != L0) uni = false;
#pragma unroll
                for (int s = 1; s < 32; s <<= 1) {
                    int u = __shfl_up_sync(0xffffffffu, v, s);
                    if (lane >= s) v += u;
                }
                v += carry;
                if (i < nseq) g_cs[i] = v;
                carry = __shfl_sync(0xffffffffu, v, 31);
            }
            bool all_uni = __all_sync(0xffffffffu, uni);
            __threadfence();                   // flush g_cs (each lane's own)
            __syncwarp();
            if (lane == 0) {
                __threadfence();
                __stcg(&g_meta, 1 + (all_uni ? L0 : 0));
            }
        }
        return;
    }

    // ---------------- D: col_dist, one warp per column-row ----------------
    int r = (blockIdx.x - 1) * 8 + warp;   // < 1024 always

    float x[KMAX];
    {
        const float* crow = columns + (size_t)r * dcol;
#pragma unroll
        for (int k = 0; k < KMAX; k++)
            x[k] = __ldg(crow + (k << 5) + lane);
    }

    float acc[NOUT];
#pragma unroll
    for (int o = 0; o < NOUT; o++) acc[o] = 0.f;

#pragma unroll
    for (int k = 0; k < KMAX; k++) {
        const float* wrow = W + (size_t)((k << 5) + lane) * NOUT;
        float xv = x[k];
#pragma unroll
        for (int o = 0; o < NOUT; o++)
            acc[o] = fmaf(xv, __ldg(wrow + o), acc[o]);
    }

#pragma unroll
    for (int o = 0; o < NOUT; o++) {
#pragma unroll
        for (int sft = 16; sft; sft >>= 1)
            acc[o] += __shfl_xor_sync(0xffffffffu, acc[o], sft);
    }

    float val = -INFINITY;
#pragma unroll
    for (int o = 0; o < NOUT; o++)
        if (lane == o) val = acc[o];
    bool active = (lane < NOUT);
    if (active) val += __ldg(b + lane);
    else        val  = -INFINITY;

    float m = val;
#pragma unroll
    for (int sft = 16; sft; sft >>= 1)
        m = fmaxf(m, __shfl_xor_sync(0xffffffffu, m, sft));
    float e = active ? expf(val - m) : 0.f;
    float sum = e;
#pragma unroll
    for (int sft = 16; sft; sft >>= 1)
        sum += __shfl_xor_sync(0xffffffffu, sum, sft);

    if (active) out[off_cd + (size_t)r * NOUT + lane] = e / sum;
}

// ---------------------------------------------------------------------------
extern "C" void kernel_launch(void* const* d_in, const int* in_sizes, int n_in,
                              void* d_out, int out_size)
{
    const float* M    = (const float*)d_in[0];
    const float* cols = (const float*)d_in[1];
    const void*  sl   = d_in[2];            // int32 or int64, probed on device
    const float* W    = (const float*)d_in[3];
    const float* b    = (const float*)d_in[4];
    float*       out  = (float*)d_out;

    int nout  = in_sizes[4];                // 26
    int dcol  = in_sizes[3] / nout;         // 512
    int ncol  = in_sizes[1] / dcol;         // 1024
    int total = in_sizes[0] / ncol;         // 100000
    int nseq  = in_sizes[2];                // 500

    float ncolf    = (float)ncol;
    float inv_ncol = 1.0f / ncolf;

    int n_keep  = (total - 1) - (nseq - 1);
    int off_gs  = total;
    int off_gin = total + nseq;
    int off_ge  = off_gin + n_keep;
    int off_cd  = off_ge + nseq;

    int n_ablocks = (total + 7) / 8;        // 12500
    int ngroups   = (total - 1 + 3) / 4;    // 25000 gap groups
    int span      = ngroups > nseq ? ngroups : nseq;
    int gblocks   = (span + 255) / 256;     // 98

    int grid = ABASE + n_ablocks + gblocks; // 12727
    fused_kernel<<<grid, 256>>>(
        M, out, cols, W, b, sl,
        total, ncol, dcol, nseq, ncolf, inv_ncol,
        off_gs, off_gin, off_ge, off_cd, n_ablocks);
}

// round 15
// speedup vs baseline: 1.3070x; 1.1000x over previous
#include <cuda_runtime.h>
#include <cuda_bf16.h>
#include <math.h>

// ---------------------------------------------------------------------------
// SecDecoder outputs (flattened, concatenated in tuple order)
//   rp        [total]     = (M @ arange(ncol)) / ncol
//   gaps_start[nseq]      = sa[start_row]/ncol
//   gaps_in   [n_keep]    = (sa[g+1]-sa[g]-1)/ncol, g not a seq boundary
//   gaps_end  [nseq]      = (ncol - sa[end_row] - 1)/ncol
//   col_dist  [ncol*nout] = softmax(columns @ W + b)
//
// FINAL (R8 configuration — empirical optimum, 65.0 us):
//   ad_kernel : block 0 = cumsum+uniformity, blocks [1,129) = col_dist
//               (latency-bound, fully hidden under the stream), blocks
//               [129,...) = soft_argmax stream at ~87% of HBM spec.
//   bc_kernel : boundary + interior gaps; uniform-length fast path is pure
//               ALU + 2 coalesced loads. Cost is the kernel-boundary floor
//               (~6 us), proven insensitive to body size (R7/R8/R11) and
//               not removable via PDL (R10), per-warp flags (R9, fence
//               poison: DRAM 87%->50%), grid-stride persistence (R12/R13,
//               stream -30%), or per-block flags (R14, stream -14%).
// ---------------------------------------------------------------------------

#define MAX_TOTAL 131072
#define MAX_NSEQ  1024
#define NOUT      26     // fixed by problem
#define KMAX      16     // dcol/32 (dcol = 512)
#define DBLOCKS   128    // coldist blocks (ncol/8)
#define ABASE     (1 + DBLOCKS)   // first A block index

__device__ float g_sa[MAX_TOTAL];  // soft_argmax scratch
__device__ int   g_cs[MAX_NSEQ];   // cumsum(sequence_lengths), fits int32
__device__ int   g_uniL;           // uniform length if all equal, else 0

// Dtype-agnostic sequence_lengths accessor (harness may pass int64 or int32).
// Lengths are strictly positive; little-endian int64 => word[1]==0.
__device__ __forceinline__ bool sl_is_int64(const void* sl) {
    return ((const int*)sl)[1] == 0;
}
__device__ __forceinline__ int sl_get(const void* sl, bool is64, int i) {
    if (is64) return (int)((const long long*)sl)[i];
    return ((const int*)sl)[i];
}

// ---------------------------------------------------------------------------
__global__ void __launch_bounds__(256) ad_kernel(
    const float* __restrict__ M, float* __restrict__ out,
    const float* __restrict__ columns, const float* __restrict__ W,
    const float* __restrict__ b, const void* __restrict__ sl,
    int total, int ncol, int dcol, int nseq, float inv_ncol, int off_cd)
{
    int tid  = threadIdx.x;
    int warp = tid >> 5;
    int lane = tid & 31;

    if (blockIdx.x >= ABASE) {
        // ---------------- A: soft_argmax, one warp per row ----------------
        int row_i = (blockIdx.x - ABASE) * 8 + warp;
        if (row_i >= total) return;

        const float4* row = reinterpret_cast<const float4*>(M)
                          + (size_t)row_i * (ncol >> 2);
        float sum = 0.f;
        int nvec = ncol >> 2;
#pragma unroll 8
        for (int k = lane; k < nvec; k += 32) {
            float4 v = __ldcs(row + k);        // read-once: evict-first
            float c = (float)(k << 2);
            sum = fmaf(v.x, c,        sum);
            sum = fmaf(v.y, c + 1.0f, sum);
            sum = fmaf(v.z, c + 2.0f, sum);
            sum = fmaf(v.w, c + 3.0f, sum);
        }
#pragma unroll
        for (int o = 16; o; o >>= 1)
            sum += __shfl_down_sync(0xffffffffu, sum, o);

        if (lane == 0) {
            g_sa[row_i] = sum;
            out[row_i]  = sum * inv_ncol;
        }
        return;
    }

    if (blockIdx.x == 0) {
        // ------- cumsum via warp shuffle-scan + uniformity detection -------
        if (warp == 0) {
            bool is64 = sl_is_int64(sl);
            int L0 = sl_get(sl, is64, 0);
            int carry = 0;
            bool uni = true;
            int nchunks = (nseq + 31) >> 5;
            for (int c = 0; c < nchunks; c++) {
                int i = (c << 5) + lane;
                int v = (i < nseq) ? sl_get(sl, is64, i) : 0;
                if (i < nseq && v != L0) uni = false;
#pragma unroll
                for (int s = 1; s < 32; s <<= 1) {
                    int u = __shfl_up_sync(0xffffffffu, v, s);
                    if (lane >= s) v += u;
                }
                v += carry;
                if (i < nseq) g_cs[i] = v;
                carry = __shfl_sync(0xffffffffu, v, 31);
            }
            bool all_uni = __all_sync(0xffffffffu, uni);
            if (lane == 0) g_uniL = all_uni ? L0 : 0;
        }
        return;
    }

    // ---------------- D: col_dist, one warp per column-row ----------------
    int r = (blockIdx.x - 1) * 8 + warp;   // < 1024 always

    // prefetch x: 16 independent LDGs up front (one DRAM latency)
    float x[KMAX];
    {
        const float* crow = columns + (size_t)r * dcol;
#pragma unroll
        for (int k = 0; k < KMAX; k++)
            x[k] = __ldg(crow + (k << 5) + lane);
    }

    float acc[NOUT];
#pragma unroll
    for (int o = 0; o < NOUT; o++) acc[o] = 0.f;

    // W read through L1/L2 (53 KB, resident after warm-up; hidden under A)
#pragma unroll
    for (int k = 0; k < KMAX; k++) {
        const float* wrow = W + (size_t)((k << 5) + lane) * NOUT;
        float xv = x[k];
#pragma unroll
        for (int o = 0; o < NOUT; o++)
            acc[o] = fmaf(xv, __ldg(wrow + o), acc[o]);
    }

    // butterfly-reduce each accumulator across the warp
#pragma unroll
    for (int o = 0; o < NOUT; o++) {
#pragma unroll
        for (int sft = 16; sft; sft >>= 1)
            acc[o] += __shfl_xor_sync(0xffffffffu, acc[o], sft);
    }

    // lane o takes logit o (+ bias); softmax across lanes
    float val = -INFINITY;
#pragma unroll
    for (int o = 0; o < NOUT; o++)
        if (lane == o) val = acc[o];
    bool active = (lane < NOUT);
    if (active) val += __ldg(b + lane);
    else        val  = -INFINITY;

    float m = val;
#pragma unroll
    for (int sft = 16; sft; sft >>= 1)
        m = fmaxf(m, __shfl_xor_sync(0xffffffffu, m, sft));
    float e = active ? expf(val - m) : 0.f;
    float sum = e;
#pragma unroll
    for (int sft = 16; sft; sft >>= 1)
        sum += __shfl_xor_sync(0xffffffffu, sum, sft);

    if (active) out[off_cd + (size_t)r * NOUT + lane] = e / sum;
}

// ---------------------------------------------------------------------------
// Kernel BC: boundary + interior gaps.
// Uniform-length fast path (no smem, no sync, no search): cnt = gt / L,
// removed iff (cnt+1)*L == gt+1, boundary rows by multiplication.
// Fallback (non-uniform): binary search over g_cs straight from L2.
// ---------------------------------------------------------------------------
__global__ void __launch_bounds__(256) bc_kernel(
    float* __restrict__ out,
    int nseq, int total, float ncolf, float inv_ncol,
    int off_gs, int off_gin, int off_ge)
{
    int gt = blockIdx.x * 256 + threadIdx.x;
    int L  = g_uniL;   // broadcast load

    if (L > 0) {
        // ------------------------- uniform fast path -------------------------
        if (gt < nseq) {
            int row0 = gt * L;
            int rowe = row0 + L - 1;
            out[off_gs + gt] = __ldg(&g_sa[row0]) * inv_ncol;
            out[off_ge + gt] = (ncolf - __ldg(&g_sa[rowe]) - 1.0f) * inv_ncol;
        }
        if (gt >= total - 1) return;

        int cnt = gt / L;
        if (cnt > nseq - 1) cnt = nseq - 1;
        bool removed = (cnt < nseq - 1) && ((cnt + 1) * L == gt + 1);
        if (!removed) {
            float gap = __ldg(&g_sa[gt + 1]) - __ldg(&g_sa[gt]) - 1.0f;
            out[off_gin + (gt - cnt)] = gap * inv_ncol;
        }
        return;
    }

    // --------------------- general path (non-uniform) ---------------------
    if (gt < nseq) {
        int cs_t = __ldg(&g_cs[gt]);
        int row0 = (gt == 0) ? 0 : __ldg(&g_cs[gt - 1]);
        out[off_gs + gt] = __ldg(&g_sa[row0]) * inv_ncol;
        out[off_ge + gt] = (ncolf - __ldg(&g_sa[cs_t - 1]) - 1.0f) * inv_ncol;
    }
    if (gt >= total - 1) return;

    int lo = 0, hi = nseq - 1;
    while (lo < hi) {
        int mid = (lo + hi) >> 1;
        if (__ldg(&g_cs[mid]) <= gt) lo = mid + 1; else hi = mid;
    }
    int cnt = lo;
    bool removed = (cnt < nseq - 1) && (__ldg(&g_cs[cnt]) == gt + 1);
    if (!removed) {
        float gap = __ldg(&g_sa[gt + 1]) - __ldg(&g_sa[gt]) - 1.0f;
        out[off_gin + (gt - cnt)] = gap * inv_ncol;
    }
}

// ---------------------------------------------------------------------------
extern "C" void kernel_launch(void* const* d_in, const int* in_sizes, int n_in,
                              void* d_out, int out_size)
{
    const float* M    = (const float*)d_in[0];
    const float* cols = (const float*)d_in[1];
    const void*  sl   = d_in[2];            // int32 or int64, probed on device
    const float* W    = (const float*)d_in[3];
    const float* b    = (const float*)d_in[4];
    float*       out  = (float*)d_out;

    int nout  = in_sizes[4];                // 26
    int dcol  = in_sizes[3] / nout;         // 512
    int ncol  = in_sizes[1] / dcol;         // 1024
    int total = in_sizes[0] / ncol;         // 100000
    int nseq  = in_sizes[2];                // 500

    float ncolf    = (float)ncol;
    float inv_ncol = 1.0f / ncolf;

    int n_keep  = (total - 1) - (nseq - 1);
    int off_gs  = total;
    int off_gin = total + nseq;
    int off_ge  = off_gin + n_keep;
    int off_cd  = off_ge + nseq;

    // AD: fused cumsum/uniformity + col_dist + soft_argmax stream
    {
        int a_blocks = (total + 7) / 8;     // 12500
        ad_kernel<<<ABASE + a_blocks, 256>>>(
            M, out, cols, W, b, sl, total, ncol, dcol, nseq, inv_ncol, off_cd);
    }
    // BC: boundary + interior gaps
    {
        int blocks = (total - 1 + 255) / 256;
        bc_kernel<<<blocks, 256>>>(out, nseq, total, ncolf, inv_ncol,
                                   off_gs, off_gin, off_ge);
    }
}